// round 16
// baseline (speedup 1.0000x reference)
#include <cuda_runtime.h>
#include <cuda_fp16.h>
#include <cstdint>

// ============================================================================
// Problem: B=4, Lq=Lk=4096, D=512, fp32. Output = (context, attn) concatenated.
// Fork-join overlap (event-based only):
//   s0: convert(b0) -> G1(b) x4 -> G3a (b0..2, gated evG2[2]) -> G3b (b3, evG2[3])
//   sB: transpose_conv, convert(b1..3), then G2(b) (+evG2[b]) after evG1[b].
// G1: CTA tile 128x64, 8 warps, 2-stage cp.async, 97 KB smem -> occupancy 2.
// ============================================================================
#define BATCH 4
#define LSEQ  4096
#define DDIM  512
#define NELEM (BATCH * LSEQ * DDIM)              // 8,388,608
#define BELEM (LSEQ * DDIM)                      // 2,097,152 per batch
#define CTX_ELEMS ((size_t)BATCH * LSEQ * DDIM)
#define PELEMS ((size_t)BATCH * LSEQ * LSEQ)     // 67,108,864

// fp16 hi/lo split scratch (device globals: sanctioned allocation-free scratch)
__device__ __align__(16) __half g_Qh[NELEM];
__device__ __align__(16) __half g_Ql[NELEM];
__device__ __align__(16) __half g_Vh[NELEM];
__device__ __align__(16) __half g_Vl[NELEM];
__device__ __align__(16) __half g_VTh[NELEM];  // [B, D, Lk] (hi only; G3 is 1-product)
__device__ __align__(16) __half g_Ph[PELEMS];  // fp16 softmaxed P (written by G2)

// ============================================================================
// Helpers
// ============================================================================
__device__ __forceinline__ uint32_t smem_to_u32(const void* smem_ptr) {
    uint32_t addr;
    asm("{ .reg .u64 tmp; cvta.to.shared.u64 tmp, %1; cvt.u32.u64 %0, tmp; }"
        : "=r"(addr) : "l"(smem_ptr));
    return addr;
}

__device__ __forceinline__ void ldsm_x4(uint32_t (&r)[4], uint32_t addr) {
    asm volatile("ldmatrix.sync.aligned.m8n8.x4.shared.b16 {%0,%1,%2,%3}, [%4];"
                 : "=r"(r[0]), "=r"(r[1]), "=r"(r[2]), "=r"(r[3]) : "r"(addr));
}

// fp32-accum HMMA
__device__ __forceinline__ void mma16816(float (&d)[4], const uint32_t (&a)[4],
                                         uint32_t b0, uint32_t b1) {
    asm volatile(
        "mma.sync.aligned.m16n8k16.row.col.f32.f16.f16.f32 "
        "{%0,%1,%2,%3}, {%4,%5,%6,%7}, {%8,%9}, {%0,%1,%2,%3};"
        : "+f"(d[0]), "+f"(d[1]), "+f"(d[2]), "+f"(d[3])
        : "r"(a[0]), "r"(a[1]), "r"(a[2]), "r"(a[3]), "r"(b0), "r"(b1));
}

// fp16-accum HMMA (for small correction products)
__device__ __forceinline__ void mma16816h(uint32_t (&d)[2], const uint32_t (&a)[4],
                                          uint32_t b0, uint32_t b1) {
    asm volatile(
        "mma.sync.aligned.m16n8k16.row.col.f16.f16.f16.f16 "
        "{%0,%1}, {%2,%3,%4,%5}, {%6,%7}, {%0,%1};"
        : "+r"(d[0]), "+r"(d[1])
        : "r"(a[0]), "r"(a[1]), "r"(a[2]), "r"(a[3]), "r"(b0), "r"(b1));
}

__device__ __forceinline__ uint32_t sw128(uint32_t off) {
    return off ^ ((off >> 3) & 0x70);
}

// cp.async 16B
__device__ __forceinline__ void cp16(uint32_t s, const void* g) {
    asm volatile("cp.async.cg.shared.global [%0], [%1], 16;" :: "r"(s), "l"(g));
}
#define CP_COMMIT() asm volatile("cp.async.commit_group;" ::: "memory")
#define CP_WAIT(n)  asm volatile("cp.async.wait_group %0;" :: "n"(n) : "memory")

// G1 smem: 2 stages x (AH 16K + AL 16K + BH 8K + BL 8K = 48 KB), 256 threads
#define G1_STAGE 49152
#define SMEM_G1 (2 * G1_STAGE + 1024)

// G3 smem: 2 stages x (AH + BH) = 2 x 32 KB, 256 threads
#define G3_STAGE 32768
#define SMEM_G3 (2 * G3_STAGE + 1024)

// ============================================================================
// P0a: elementwise convert Q,V -> fp16 hi/lo for ONE batch (8192 blocks x 256)
// ============================================================================
__global__ void convert_qv(const float* __restrict__ Q, const float* __restrict__ V,
                           int b) {
    size_t i = (size_t)b * BELEM + (size_t)blockIdx.x * 256 + threadIdx.x;
    float q = Q[i];
    __half qh = __float2half_rn(q);
    g_Qh[i] = qh;
    g_Ql[i] = __float2half_rn(q - __half2float(qh));
    float v = V[i];
    __half vh = __float2half_rn(v);
    g_Vh[i] = vh;
    g_Vl[i] = __float2half_rn(v - __half2float(vh));
}

// ============================================================================
// P0b: transpose+convert V -> VT[b][d][k] fp16 (hi only). Forked stream.
// ============================================================================
__global__ void transpose_conv(const float* __restrict__ V) {
    __shared__ float tile[32][33];
    int b = blockIdx.z;
    int k0 = blockIdx.x * 32, d0 = blockIdx.y * 32;
    int tx = threadIdx.x, ty = threadIdx.y;  // 32 x 8
#pragma unroll
    for (int j = 0; j < 4; j++) {
        tile[ty + 8 * j][tx] =
            V[((size_t)b * LSEQ + k0 + ty + 8 * j) * DDIM + d0 + tx];
    }
    __syncthreads();
#pragma unroll
    for (int j = 0; j < 4; j++) {
        int d = d0 + ty + 8 * j, k = k0 + tx;
        size_t o = ((size_t)b * DDIM + d) * LSEQ + k;
        g_VTh[o] = __float2half_rn(tile[tx][ty + 8 * j]);
    }
}

// Tiny probe so the ncu fixed-skip profiling slot stays near g1_scores.
__global__ void probe_kernel() {}

// ============================================================================
// cp.async tile loader: ROWS rows x 64 halfs, SW128 swizzled, NT threads
// ============================================================================
template <int NT, int ROWS>
__device__ __forceinline__ void tile_cp(uint32_t sbase,
                                        const __half* __restrict__ gsrc,
                                        int rowStrideU4, int chunk, int tid) {
    const uint4* g = reinterpret_cast<const uint4*>(gsrc);
#pragma unroll
    for (int it = 0; it < ROWS * 8 / NT; it++) {
        int idx = tid + NT * it;
        int r = idx >> 3, s = idx & 7;
        cp16(sbase + sw128((uint32_t)(r * 128 + s * 16)),
             g + (size_t)r * rowStrideU4 + (size_t)chunk * 8 + s);
    }
}

// ============================================================================
// G1 warp MMA core. 8 warps (4m x 2n), warp tile 32(m) x 32(n).
// Stage layout: AH=0, AL=+16384, BH=+32768, BL=+40960.
// hh -> fp32 acc; hl + lh corrections -> fp16 acc.
// ============================================================================
struct Frag {
    uint32_t ah[2][4], al[2][4];
    uint32_t bh[2][4], bl[2][4];
};

__device__ __forceinline__ void load_frags(Frag& f, uint32_t tA, uint32_t tB,
                                           int mw, int nw, int kk, int lane) {
    int kb = kk * 32 + ((lane >> 4) << 4);
#pragma unroll
    for (int mb = 0; mb < 2; mb++) {
        int row = mw * 32 + mb * 16 + (lane & 15);
        uint32_t addr = tA + row * 128 + (kb ^ ((row & 7) << 4));
        ldsm_x4(f.ah[mb], addr);
        ldsm_x4(f.al[mb], addr + 16384);
    }
#pragma unroll
    for (int p = 0; p < 2; p++) {
        int row = nw * 32 + p * 16 + ((lane >> 3 & 1) << 3) + (lane & 7);
        uint32_t addr = tB + row * 128 + (kb ^ ((row & 7) << 4));
        ldsm_x4(f.bh[p], addr);
        ldsm_x4(f.bl[p], addr + 8192);    // BL sits 8 KB above BH (64-row tile)
    }
}

__device__ __forceinline__ void mma_g1(float (&accf)[2][4][4],
                                       uint32_t (&acch)[2][4][2], const Frag& f) {
#pragma unroll
    for (int mb = 0; mb < 2; mb++)
#pragma unroll
        for (int nb = 0; nb < 4; nb++) {
            int p = nb >> 1, s = nb & 1;
            mma16816(accf[mb][nb], f.ah[mb], f.bh[p][s], f.bh[p][s + 2]);
            mma16816h(acch[mb][nb], f.ah[mb], f.bl[p][s], f.bl[p][s + 2]);
            mma16816h(acch[mb][nb], f.al[mb], f.bh[p][s], f.bh[p][s + 2]);
        }
}

// ============================================================================
// G3 warp MMA core (single product: P_h x V_h). 8 warps, warp tile 32x64.
// ============================================================================
struct FragG3 {
    uint32_t ah[2][4];
    uint32_t bh[4][4];
};

__device__ __forceinline__ void load_frags_g3(FragG3& f, uint32_t tA, uint32_t tB,
                                              int mw, int nw, int kk, int lane) {
    int kb = kk * 32 + ((lane >> 4) << 4);
#pragma unroll
    for (int mb = 0; mb < 2; mb++) {
        int row = mw * 32 + mb * 16 + (lane & 15);
        ldsm_x4(f.ah[mb], tA + row * 128 + (kb ^ ((row & 7) << 4)));
    }
#pragma unroll
    for (int p = 0; p < 4; p++) {
        int row = nw * 64 + p * 16 + ((lane >> 3 & 1) << 3) + (lane & 7);
        ldsm_x4(f.bh[p], tB + row * 128 + (kb ^ ((row & 7) << 4)));
    }
}

__device__ __forceinline__ void mma_1prod(float (&acc)[2][8][4], const FragG3& f) {
#pragma unroll
    for (int mb = 0; mb < 2; mb++)
#pragma unroll
        for (int nb = 0; nb < 8; nb++) {
            int p = nb >> 1, s = nb & 1;
            mma16816(acc[mb][nb], f.ah[mb], f.bh[p][s], f.bh[p][s + 2]);
        }
}

// ============================================================================
// G1: raw scores S = Q @ V^T for ONE batch. CTA tile 128(q) x 64(k),
// K=512 in 8 chunks, 256 threads (8 warps, 4m x 2n of 32x32), 2-stage
// cp.async (occupancy 2), one barrier per chunk. grid (kt=64, qt=32).
// ============================================================================
__global__ void __launch_bounds__(256, 2) g1_scores(float* __restrict__ attn, int b) {
    extern __shared__ char smem[];
    uint32_t sb0 = smem_to_u32(smem);
    uint32_t tb = (sb0 + 1023) & ~1023u;
    int tid = threadIdx.x, wid = tid >> 5, lane = tid & 31;
    int mw = wid & 3, nw = wid >> 2;
    int kt = blockIdx.x, qt = blockIdx.y;

    const __half* pQh = g_Qh + ((size_t)(b * LSEQ + qt * 128)) * DDIM;
    const __half* pQl = g_Ql + ((size_t)(b * LSEQ + qt * 128)) * DDIM;
    const __half* pVh = g_Vh + ((size_t)(b * LSEQ + kt * 64)) * DDIM;
    const __half* pVl = g_Vl + ((size_t)(b * LSEQ + kt * 64)) * DDIM;

    float accf[2][4][4];
    uint32_t acch[2][4][2];
#pragma unroll
    for (int i = 0; i < 2; i++)
#pragma unroll
        for (int j = 0; j < 4; j++) {
#pragma unroll
            for (int k = 0; k < 4; k++) accf[i][j][k] = 0.f;
            acch[i][j][0] = 0u;
            acch[i][j][1] = 0u;
        }

    auto issue = [&](int c) {
        uint32_t st = tb + (uint32_t)(c & 1) * G1_STAGE;
        tile_cp<256, 128>(st,         pQh, DDIM / 8, c, tid);
        tile_cp<256, 128>(st + 16384, pQl, DDIM / 8, c, tid);
        tile_cp<256, 64> (st + 32768, pVh, DDIM / 8, c, tid);
        tile_cp<256, 64> (st + 40960, pVl, DDIM / 8, c, tid);
        CP_COMMIT();
    };

    issue(0);
    for (int c = 0; c < 8; c++) {
        CP_WAIT(0);            // chunk c resident (only group pending)
        __syncthreads();       // single barrier/chunk: all warps done with c-1
        if (c < 7) issue(c + 1);   // overwrites stage (c-1)&1 — safe
        uint32_t st = tb + (uint32_t)(c & 1) * G1_STAGE;
#pragma unroll
        for (int kk = 0; kk < 4; kk++) {
            Frag f;
            load_frags(f, st, st + 32768, mw, nw, kk, lane);
            mma_g1(accf, acch, f);
        }
    }

    // Epilogue: merge fp16 corrections into fp32 and write raw scores
    int gid = lane >> 2, tig = lane & 3;
    size_t base = ((size_t)(b * LSEQ + qt * 128 + mw * 32)) * LSEQ
                + (size_t)kt * 64 + nw * 32;
#pragma unroll
    for (int mb = 0; mb < 2; mb++)
#pragma unroll
        for (int nb = 0; nb < 4; nb++) {
            float2 c01 = __half22float2(*reinterpret_cast<const __half2*>(&acch[mb][nb][0]));
            float2 c23 = __half22float2(*reinterpret_cast<const __half2*>(&acch[mb][nb][1]));
            size_t o0 = base + (size_t)(mb * 16 + gid) * LSEQ + nb * 8 + tig * 2;
            *reinterpret_cast<float2*>(&attn[o0]) =
                make_float2(accf[mb][nb][0] + c01.x, accf[mb][nb][1] + c01.y);
            *reinterpret_cast<float2*>(&attn[o0 + 8 * LSEQ]) =
                make_float2(accf[mb][nb][2] + c23.x, accf[mb][nb][3] + c23.y);
        }
}

// ============================================================================
// G2: single-pass register-resident row softmax for ONE batch (4096 rows).
// Writes fp32 p to attn AND fp16 p to g_Ph. Co-resides with G1 while overlapping.
// ============================================================================
__global__ void __launch_bounds__(256) g2_softmax(float* __restrict__ attn, int b) {
    __shared__ float red[16];
    int tid = threadIdx.x, lane = tid & 31, w = tid >> 5;
    size_t rrow = (size_t)(b * LSEQ + blockIdx.x) * LSEQ;
    float4* row = reinterpret_cast<float4*>(attn + rrow);
    __half2* hrow = reinterpret_cast<__half2*>(g_Ph + rrow);

    float4 v[4];
#pragma unroll
    for (int i = 0; i < 4; i++) v[i] = row[tid + i * 256];

    float m = -3.4e38f;
#pragma unroll
    for (int i = 0; i < 4; i++)
        m = fmaxf(m, fmaxf(fmaxf(v[i].x, v[i].y), fmaxf(v[i].z, v[i].w)));
#pragma unroll
    for (int o = 16; o; o >>= 1) m = fmaxf(m, __shfl_xor_sync(~0u, m, o));
    if (lane == 0) red[w] = m;
    __syncthreads();
    m = red[0];
#pragma unroll
    for (int i = 1; i < 8; i++) m = fmaxf(m, red[i]);

    float z = 0.f;
#pragma unroll
    for (int i = 0; i < 4; i++) {
        v[i].x = __expf(v[i].x - m);
        v[i].y = __expf(v[i].y - m);
        v[i].z = __expf(v[i].z - m);
        v[i].w = __expf(v[i].w - m);
        z += (v[i].x + v[i].y) + (v[i].z + v[i].w);
    }
#pragma unroll
    for (int o = 16; o; o >>= 1) z += __shfl_xor_sync(~0u, z, o);
    if (lane == 0) red[8 + w] = z;
    __syncthreads();
    z = 0.f;
#pragma unroll
    for (int i = 0; i < 8; i++) z += red[8 + i];
    float iz = 1.0f / z;

#pragma unroll
    for (int i = 0; i < 4; i++) {
        v[i].x *= iz; v[i].y *= iz; v[i].z *= iz; v[i].w *= iz;
        row[tid + i * 256] = v[i];
        hrow[2 * (tid + i * 256)]     = __floats2half2_rn(v[i].x, v[i].y);
        hrow[2 * (tid + i * 256) + 1] = __floats2half2_rn(v[i].z, v[i].w);
    }
}

// ============================================================================
// G3: context C = P @ V for batches [b0, b0+nz). CTA tile 128 x 128,
// K=4096/64 chunks, single-product, 2-stage cp.async, one barrier/chunk.
// grid (dt=4, qt=32, nz), 256 threads.
// ============================================================================
__global__ void __launch_bounds__(256) g3_context(float* __restrict__ ctx, int b0) {
    extern __shared__ char smem[];
    uint32_t sb0 = smem_to_u32(smem);
    uint32_t tb = (sb0 + 1023) & ~1023u;
    int tid = threadIdx.x, wid = tid >> 5, lane = tid & 31;
    int mw = wid & 3, nw = wid >> 2;
    int dt = blockIdx.x, qt = blockIdx.y, b = blockIdx.z + b0;

    const __half* pA  = g_Ph  + ((size_t)(b * LSEQ + qt * 128)) * LSEQ;
    const __half* pBh = g_VTh + ((size_t)(b * DDIM + dt * 128)) * LSEQ;

    float acc[2][8][4];
#pragma unroll
    for (int i = 0; i < 2; i++)
#pragma unroll
        for (int j = 0; j < 8; j++)
#pragma unroll
            for (int k = 0; k < 4; k++) acc[i][j][k] = 0.f;

    auto issue = [&](int c) {
        uint32_t st = tb + (uint32_t)(c & 1) * G3_STAGE;
        tile_cp<256, 128>(st,         pA,  LSEQ / 8, c, tid);
        tile_cp<256, 128>(st + 16384, pBh, LSEQ / 8, c, tid);
        CP_COMMIT();
    };

    issue(0);
    for (int c = 0; c < 64; c++) {
        CP_WAIT(0);            // chunk c resident (only group pending)
        __syncthreads();       // single barrier/chunk
        if (c < 63) issue(c + 1);
        uint32_t st = tb + (uint32_t)(c & 1) * G3_STAGE;
#pragma unroll
        for (int kk = 0; kk < 4; kk++) {
            FragG3 f;
            load_frags_g3(f, st, st + 16384, mw, nw, kk, lane);
            mma_1prod(acc, f);
        }
    }

    // Epilogue: write context
    int gid = lane >> 2, tig = lane & 3;
    size_t base = ((size_t)(b * LSEQ + qt * 128 + mw * 32)) * DDIM
                + (size_t)dt * 128 + nw * 64;
#pragma unroll
    for (int mb = 0; mb < 2; mb++)
#pragma unroll
        for (int nb = 0; nb < 8; nb++) {
            size_t o0 = base + (size_t)(mb * 16 + gid) * DDIM + nb * 8 + tig * 2;
            *reinterpret_cast<float2*>(&ctx[o0]) =
                make_float2(acc[mb][nb][0], acc[mb][nb][1]);
            *reinterpret_cast<float2*>(&ctx[o0 + 8 * DDIM]) =
                make_float2(acc[mb][nb][2], acc[mb][nb][3]);
        }
}

// ============================================================================
// Launch: event-based fork-join (graph-capture safe; no device spin).
//   s0: convert(b0), probe, [wait evC[b]] G1(b) x4,
//       [wait evG2[2]] G3a(b0..2), [wait evG2[3]] G3b(b3).
//   sB: transpose_conv, convert(b1..3)+evC, then G2(b)+evG2[b] after evG1[b].
// Streams/events created per call and leaked (host-side only; ~2 calls).
// ============================================================================
extern "C" void kernel_launch(void* const* d_in, const int* in_sizes, int n_in,
                              void* d_out, int out_size) {
    (void)in_sizes; (void)n_in; (void)out_size;
    const float* query = (const float*)d_in[0];
    const float* value = (const float*)d_in[1];
    float* out = (float*)d_out;
    float* ctx  = out;               // context first
    float* attn = out + CTX_ELEMS;   // then attn

    cudaFuncSetAttribute(g1_scores,  cudaFuncAttributeMaxDynamicSharedMemorySize, SMEM_G1);
    cudaFuncSetAttribute(g3_context, cudaFuncAttributeMaxDynamicSharedMemorySize, SMEM_G3);

    cudaStream_t sB;
    cudaStreamCreateWithFlags(&sB, cudaStreamNonBlocking);
    cudaEvent_t evFork, evC[BATCH], evG1[BATCH], evG2[BATCH];
    cudaEventCreateWithFlags(&evFork, cudaEventDisableTiming);
    for (int b = 0; b < BATCH; b++) {
        cudaEventCreateWithFlags(&evC[b], cudaEventDisableTiming);
        cudaEventCreateWithFlags(&evG1[b], cudaEventDisableTiming);
        cudaEventCreateWithFlags(&evG2[b], cudaEventDisableTiming);
    }

    // Fork: sB handles transpose (raw V only) + converts for batches 1..3,
    // all overlapping G1(b0) on s0.
    cudaEventRecord(evFork, 0);
    cudaStreamWaitEvent(sB, evFork, 0);
    transpose_conv<<<dim3(LSEQ / 32, DDIM / 32, BATCH), dim3(32, 8), 0, sB>>>(value);
    for (int b = 1; b < BATCH; b++) {
        convert_qv<<<BELEM / 256, 256, 0, sB>>>(query, value, b);
        cudaEventRecord(evC[b], sB);
    }

    // s0: only batch 0's convert sits on the critical path.
    convert_qv<<<BELEM / 256, 256>>>(query, value, 0);
    probe_kernel<<<1, 32>>>();

    for (int b = 0; b < BATCH; b++) {
        if (b > 0) cudaStreamWaitEvent(0, evC[b], 0);
        g1_scores<<<dim3(64, 32), 256, SMEM_G1>>>(attn, b);
        cudaEventRecord(evG1[b], 0);
        cudaStreamWaitEvent(sB, evG1[b], 0);
        g2_softmax<<<LSEQ, 256, 0, sB>>>(attn, b);
        cudaEventRecord(evG2[b], sB);
    }

    // Split join: G3a (batches 0..2) only needs evG2[2] (sB is in-order, so
    // it implies G2(0..2) complete) — launches the moment G1(b3) frees the SMs.
    // G3b (batch 3) waits for evG2[3] and fills in ~24 us later.
    cudaStreamWaitEvent(0, evG2[2], 0);
    g3_context<<<dim3(4, 32, 3), 256, SMEM_G3>>>(ctx, 0);
    cudaStreamWaitEvent(0, evG2[3], 0);
    g3_context<<<dim3(4, 32, 1), 256, SMEM_G3>>>(ctx, 3);
    // Streams/events intentionally leaked (capture-referenced; ~2 calls total).
}

// round 17
// speedup vs baseline: 1.0193x; 1.0193x over previous
#include <cuda_runtime.h>
#include <cuda_fp16.h>
#include <cstdint>

// ============================================================================
// Problem: B=4, Lq=Lk=4096, D=512, fp32. Output = (context, attn) concatenated.
// Fork-join overlap (event-based only):
//   s0: convert(b0) -> G1(b) x4 -> (join) -> G3 (monolithic)
//   sB: transpose_conv, convert(b1..3), then G2(b) after event of G1(b).
// G1: CTA tile 128x64, 8 warps, 2-stage cp.async, 97 KB smem -> occupancy 2.
// ============================================================================
#define BATCH 4
#define LSEQ  4096
#define DDIM  512
#define NELEM (BATCH * LSEQ * DDIM)              // 8,388,608
#define BELEM (LSEQ * DDIM)                      // 2,097,152 per batch
#define CTX_ELEMS ((size_t)BATCH * LSEQ * DDIM)
#define PELEMS ((size_t)BATCH * LSEQ * LSEQ)     // 67,108,864

// fp16 hi/lo split scratch (device globals: sanctioned allocation-free scratch)
__device__ __align__(16) __half g_Qh[NELEM];
__device__ __align__(16) __half g_Ql[NELEM];
__device__ __align__(16) __half g_Vh[NELEM];
__device__ __align__(16) __half g_Vl[NELEM];
__device__ __align__(16) __half g_VTh[NELEM];  // [B, D, Lk] (hi only; G3 is 1-product)
__device__ __align__(16) __half g_Ph[PELEMS];  // fp16 softmaxed P (written by G2)

// ============================================================================
// Helpers
// ============================================================================
__device__ __forceinline__ uint32_t smem_to_u32(const void* smem_ptr) {
    uint32_t addr;
    asm("{ .reg .u64 tmp; cvta.to.shared.u64 tmp, %1; cvt.u32.u64 %0, tmp; }"
        : "=r"(addr) : "l"(smem_ptr));
    return addr;
}

__device__ __forceinline__ void ldsm_x4(uint32_t (&r)[4], uint32_t addr) {
    asm volatile("ldmatrix.sync.aligned.m8n8.x4.shared.b16 {%0,%1,%2,%3}, [%4];"
                 : "=r"(r[0]), "=r"(r[1]), "=r"(r[2]), "=r"(r[3]) : "r"(addr));
}

// fp32-accum HMMA
__device__ __forceinline__ void mma16816(float (&d)[4], const uint32_t (&a)[4],
                                         uint32_t b0, uint32_t b1) {
    asm volatile(
        "mma.sync.aligned.m16n8k16.row.col.f32.f16.f16.f32 "
        "{%0,%1,%2,%3}, {%4,%5,%6,%7}, {%8,%9}, {%0,%1,%2,%3};"
        : "+f"(d[0]), "+f"(d[1]), "+f"(d[2]), "+f"(d[3])
        : "r"(a[0]), "r"(a[1]), "r"(a[2]), "r"(a[3]), "r"(b0), "r"(b1));
}

// fp16-accum HMMA (for small correction products)
__device__ __forceinline__ void mma16816h(uint32_t (&d)[2], const uint32_t (&a)[4],
                                          uint32_t b0, uint32_t b1) {
    asm volatile(
        "mma.sync.aligned.m16n8k16.row.col.f16.f16.f16.f16 "
        "{%0,%1}, {%2,%3,%4,%5}, {%6,%7}, {%0,%1};"
        : "+r"(d[0]), "+r"(d[1])
        : "r"(a[0]), "r"(a[1]), "r"(a[2]), "r"(a[3]), "r"(b0), "r"(b1));
}

__device__ __forceinline__ uint32_t sw128(uint32_t off) {
    return off ^ ((off >> 3) & 0x70);
}

// cp.async 16B
__device__ __forceinline__ void cp16(uint32_t s, const void* g) {
    asm volatile("cp.async.cg.shared.global [%0], [%1], 16;" :: "r"(s), "l"(g));
}
#define CP_COMMIT() asm volatile("cp.async.commit_group;" ::: "memory")
#define CP_WAIT(n)  asm volatile("cp.async.wait_group %0;" :: "n"(n) : "memory")

// G1 smem: 2 stages x (AH 16K + AL 16K + BH 8K + BL 8K = 48 KB), 256 threads
#define G1_STAGE 49152
#define SMEM_G1 (2 * G1_STAGE + 1024)

// G3 smem: 2 stages x (AH + BH) = 2 x 32 KB, 256 threads
#define G3_STAGE 32768
#define SMEM_G3 (2 * G3_STAGE + 1024)

// ============================================================================
// P0a: elementwise convert Q,V -> fp16 hi/lo for ONE batch (8192 blocks x 256)
// ============================================================================
__global__ void convert_qv(const float* __restrict__ Q, const float* __restrict__ V,
                           int b) {
    size_t i = (size_t)b * BELEM + (size_t)blockIdx.x * 256 + threadIdx.x;
    float q = Q[i];
    __half qh = __float2half_rn(q);
    g_Qh[i] = qh;
    g_Ql[i] = __float2half_rn(q - __half2float(qh));
    float v = V[i];
    __half vh = __float2half_rn(v);
    g_Vh[i] = vh;
    g_Vl[i] = __float2half_rn(v - __half2float(vh));
}

// ============================================================================
// P0b: transpose+convert V -> VT[b][d][k] fp16 (hi only). Forked stream.
// ============================================================================
__global__ void transpose_conv(const float* __restrict__ V) {
    __shared__ float tile[32][33];
    int b = blockIdx.z;
    int k0 = blockIdx.x * 32, d0 = blockIdx.y * 32;
    int tx = threadIdx.x, ty = threadIdx.y;  // 32 x 8
#pragma unroll
    for (int j = 0; j < 4; j++) {
        tile[ty + 8 * j][tx] =
            V[((size_t)b * LSEQ + k0 + ty + 8 * j) * DDIM + d0 + tx];
    }
    __syncthreads();
#pragma unroll
    for (int j = 0; j < 4; j++) {
        int d = d0 + ty + 8 * j, k = k0 + tx;
        size_t o = ((size_t)b * DDIM + d) * LSEQ + k;
        g_VTh[o] = __float2half_rn(tile[tx][ty + 8 * j]);
    }
}

// ============================================================================
// cp.async tile loader: ROWS rows x 64 halfs, SW128 swizzled, NT threads
// ============================================================================
template <int NT, int ROWS>
__device__ __forceinline__ void tile_cp(uint32_t sbase,
                                        const __half* __restrict__ gsrc,
                                        int rowStrideU4, int chunk, int tid) {
    const uint4* g = reinterpret_cast<const uint4*>(gsrc);
#pragma unroll
    for (int it = 0; it < ROWS * 8 / NT; it++) {
        int idx = tid + NT * it;
        int r = idx >> 3, s = idx & 7;
        cp16(sbase + sw128((uint32_t)(r * 128 + s * 16)),
             g + (size_t)r * rowStrideU4 + (size_t)chunk * 8 + s);
    }
}

// ============================================================================
// G1 warp MMA core. 8 warps (4m x 2n), warp tile 32(m) x 32(n).
// Stage layout: AH=0, AL=+16384, BH=+32768, BL=+40960.
// hh -> fp32 acc; hl + lh corrections -> fp16 acc.
// ============================================================================
struct Frag {
    uint32_t ah[2][4], al[2][4];
    uint32_t bh[2][4], bl[2][4];
};

__device__ __forceinline__ void load_frags(Frag& f, uint32_t tA, uint32_t tB,
                                           int mw, int nw, int kk, int lane) {
    int kb = kk * 32 + ((lane >> 4) << 4);
#pragma unroll
    for (int mb = 0; mb < 2; mb++) {
        int row = mw * 32 + mb * 16 + (lane & 15);
        uint32_t addr = tA + row * 128 + (kb ^ ((row & 7) << 4));
        ldsm_x4(f.ah[mb], addr);
        ldsm_x4(f.al[mb], addr + 16384);
    }
#pragma unroll
    for (int p = 0; p < 2; p++) {
        int row = nw * 32 + p * 16 + ((lane >> 3 & 1) << 3) + (lane & 7);
        uint32_t addr = tB + row * 128 + (kb ^ ((row & 7) << 4));
        ldsm_x4(f.bh[p], addr);
        ldsm_x4(f.bl[p], addr + 8192);    // BL sits 8 KB above BH (64-row tile)
    }
}

__device__ __forceinline__ void mma_g1(float (&accf)[2][4][4],
                                       uint32_t (&acch)[2][4][2], const Frag& f) {
#pragma unroll
    for (int mb = 0; mb < 2; mb++)
#pragma unroll
        for (int nb = 0; nb < 4; nb++) {
            int p = nb >> 1, s = nb & 1;
            mma16816(accf[mb][nb], f.ah[mb], f.bh[p][s], f.bh[p][s + 2]);
            mma16816h(acch[mb][nb], f.ah[mb], f.bl[p][s], f.bl[p][s + 2]);
            mma16816h(acch[mb][nb], f.al[mb], f.bh[p][s], f.bh[p][s + 2]);
        }
}

// ============================================================================
// G3 warp MMA core (single product: P_h x V_h). 8 warps, warp tile 32x64.
// ============================================================================
struct FragG3 {
    uint32_t ah[2][4];
    uint32_t bh[4][4];
};

__device__ __forceinline__ void load_frags_g3(FragG3& f, uint32_t tA, uint32_t tB,
                                              int mw, int nw, int kk, int lane) {
    int kb = kk * 32 + ((lane >> 4) << 4);
#pragma unroll
    for (int mb = 0; mb < 2; mb++) {
        int row = mw * 32 + mb * 16 + (lane & 15);
        ldsm_x4(f.ah[mb], tA + row * 128 + (kb ^ ((row & 7) << 4)));
    }
#pragma unroll
    for (int p = 0; p < 4; p++) {
        int row = nw * 64 + p * 16 + ((lane >> 3 & 1) << 3) + (lane & 7);
        ldsm_x4(f.bh[p], tB + row * 128 + (kb ^ ((row & 7) << 4)));
    }
}

__device__ __forceinline__ void mma_1prod(float (&acc)[2][8][4], const FragG3& f) {
#pragma unroll
    for (int mb = 0; mb < 2; mb++)
#pragma unroll
        for (int nb = 0; nb < 8; nb++) {
            int p = nb >> 1, s = nb & 1;
            mma16816(acc[mb][nb], f.ah[mb], f.bh[p][s], f.bh[p][s + 2]);
        }
}

// ============================================================================
// G1: raw scores S = Q @ V^T for ONE batch. CTA tile 128(q) x 64(k),
// K=512 in 8 chunks, 256 threads (8 warps, 4m x 2n of 32x32), 2-stage
// cp.async (occupancy 2), one barrier per chunk. grid (kt=64, qt=32).
// ============================================================================
__global__ void __launch_bounds__(256, 2) g1_scores(float* __restrict__ attn, int b) {
    extern __shared__ char smem[];
    uint32_t sb0 = smem_to_u32(smem);
    uint32_t tb = (sb0 + 1023) & ~1023u;
    int tid = threadIdx.x, wid = tid >> 5, lane = tid & 31;
    int mw = wid & 3, nw = wid >> 2;
    int kt = blockIdx.x, qt = blockIdx.y;

    const __half* pQh = g_Qh + ((size_t)(b * LSEQ + qt * 128)) * DDIM;
    const __half* pQl = g_Ql + ((size_t)(b * LSEQ + qt * 128)) * DDIM;
    const __half* pVh = g_Vh + ((size_t)(b * LSEQ + kt * 64)) * DDIM;
    const __half* pVl = g_Vl + ((size_t)(b * LSEQ + kt * 64)) * DDIM;

    float accf[2][4][4];
    uint32_t acch[2][4][2];
#pragma unroll
    for (int i = 0; i < 2; i++)
#pragma unroll
        for (int j = 0; j < 4; j++) {
#pragma unroll
            for (int k = 0; k < 4; k++) accf[i][j][k] = 0.f;
            acch[i][j][0] = 0u;
            acch[i][j][1] = 0u;
        }

    auto issue = [&](int c) {
        uint32_t st = tb + (uint32_t)(c & 1) * G1_STAGE;
        tile_cp<256, 128>(st,         pQh, DDIM / 8, c, tid);
        tile_cp<256, 128>(st + 16384, pQl, DDIM / 8, c, tid);
        tile_cp<256, 64> (st + 32768, pVh, DDIM / 8, c, tid);
        tile_cp<256, 64> (st + 40960, pVl, DDIM / 8, c, tid);
        CP_COMMIT();
    };

    issue(0);
    for (int c = 0; c < 8; c++) {
        CP_WAIT(0);            // chunk c resident (only group pending)
        __syncthreads();       // single barrier/chunk: all warps done with c-1
        if (c < 7) issue(c + 1);   // overwrites stage (c-1)&1 — safe
        uint32_t st = tb + (uint32_t)(c & 1) * G1_STAGE;
#pragma unroll
        for (int kk = 0; kk < 4; kk++) {
            Frag f;
            load_frags(f, st, st + 32768, mw, nw, kk, lane);
            mma_g1(accf, acch, f);
        }
    }

    // Epilogue: merge fp16 corrections into fp32 and write raw scores
    int gid = lane >> 2, tig = lane & 3;
    size_t base = ((size_t)(b * LSEQ + qt * 128 + mw * 32)) * LSEQ
                + (size_t)kt * 64 + nw * 32;
#pragma unroll
    for (int mb = 0; mb < 2; mb++)
#pragma unroll
        for (int nb = 0; nb < 4; nb++) {
            float2 c01 = __half22float2(*reinterpret_cast<const __half2*>(&acch[mb][nb][0]));
            float2 c23 = __half22float2(*reinterpret_cast<const __half2*>(&acch[mb][nb][1]));
            size_t o0 = base + (size_t)(mb * 16 + gid) * LSEQ + nb * 8 + tig * 2;
            *reinterpret_cast<float2*>(&attn[o0]) =
                make_float2(accf[mb][nb][0] + c01.x, accf[mb][nb][1] + c01.y);
            *reinterpret_cast<float2*>(&attn[o0 + 8 * LSEQ]) =
                make_float2(accf[mb][nb][2] + c23.x, accf[mb][nb][3] + c23.y);
        }
}

// ============================================================================
// G2: single-pass register-resident row softmax for ONE batch (4096 rows).
// Writes fp32 p to attn AND fp16 p to g_Ph. Co-resides with G1 while overlapping.
// ============================================================================
__global__ void __launch_bounds__(256) g2_softmax(float* __restrict__ attn, int b) {
    __shared__ float red[16];
    int tid = threadIdx.x, lane = tid & 31, w = tid >> 5;
    size_t rrow = (size_t)(b * LSEQ + blockIdx.x) * LSEQ;
    float4* row = reinterpret_cast<float4*>(attn + rrow);
    __half2* hrow = reinterpret_cast<__half2*>(g_Ph + rrow);

    float4 v[4];
#pragma unroll
    for (int i = 0; i < 4; i++) v[i] = row[tid + i * 256];

    float m = -3.4e38f;
#pragma unroll
    for (int i = 0; i < 4; i++)
        m = fmaxf(m, fmaxf(fmaxf(v[i].x, v[i].y), fmaxf(v[i].z, v[i].w)));
#pragma unroll
    for (int o = 16; o; o >>= 1) m = fmaxf(m, __shfl_xor_sync(~0u, m, o));
    if (lane == 0) red[w] = m;
    __syncthreads();
    m = red[0];
#pragma unroll
    for (int i = 1; i < 8; i++) m = fmaxf(m, red[i]);

    float z = 0.f;
#pragma unroll
    for (int i = 0; i < 4; i++) {
        v[i].x = __expf(v[i].x - m);
        v[i].y = __expf(v[i].y - m);
        v[i].z = __expf(v[i].z - m);
        v[i].w = __expf(v[i].w - m);
        z += (v[i].x + v[i].y) + (v[i].z + v[i].w);
    }
#pragma unroll
    for (int o = 16; o; o >>= 1) z += __shfl_xor_sync(~0u, z, o);
    if (lane == 0) red[8 + w] = z;
    __syncthreads();
    z = 0.f;
#pragma unroll
    for (int i = 0; i < 8; i++) z += red[8 + i];
    float iz = 1.0f / z;

#pragma unroll
    for (int i = 0; i < 4; i++) {
        v[i].x *= iz; v[i].y *= iz; v[i].z *= iz; v[i].w *= iz;
        row[tid + i * 256] = v[i];
        hrow[2 * (tid + i * 256)]     = __floats2half2_rn(v[i].x, v[i].y);
        hrow[2 * (tid + i * 256) + 1] = __floats2half2_rn(v[i].z, v[i].w);
    }
}

// ============================================================================
// G3: context C = P @ V, MONOLITHIC (after join). CTA tile 128 x 128,
// K=4096/64 chunks, single-product, 2-stage cp.async, one barrier/chunk.
// grid (dt=4, qt=32, b=4), 256 threads.
// ============================================================================
__global__ void __launch_bounds__(256) g3_context(float* __restrict__ ctx) {
    extern __shared__ char smem[];
    uint32_t sb0 = smem_to_u32(smem);
    uint32_t tb = (sb0 + 1023) & ~1023u;
    int tid = threadIdx.x, wid = tid >> 5, lane = tid & 31;
    int mw = wid & 3, nw = wid >> 2;
    int dt = blockIdx.x, qt = blockIdx.y, b = blockIdx.z;

    const __half* pA  = g_Ph  + ((size_t)(b * LSEQ + qt * 128)) * LSEQ;
    const __half* pBh = g_VTh + ((size_t)(b * DDIM + dt * 128)) * LSEQ;

    float acc[2][8][4];
#pragma unroll
    for (int i = 0; i < 2; i++)
#pragma unroll
        for (int j = 0; j < 8; j++)
#pragma unroll
            for (int k = 0; k < 4; k++) acc[i][j][k] = 0.f;

    auto issue = [&](int c) {
        uint32_t st = tb + (uint32_t)(c & 1) * G3_STAGE;
        tile_cp<256, 128>(st,         pA,  LSEQ / 8, c, tid);
        tile_cp<256, 128>(st + 16384, pBh, LSEQ / 8, c, tid);
        CP_COMMIT();
    };

    issue(0);
    for (int c = 0; c < 64; c++) {
        CP_WAIT(0);            // chunk c resident (only group pending)
        __syncthreads();       // single barrier/chunk
        if (c < 63) issue(c + 1);
        uint32_t st = tb + (uint32_t)(c & 1) * G3_STAGE;
#pragma unroll
        for (int kk = 0; kk < 4; kk++) {
            FragG3 f;
            load_frags_g3(f, st, st + 16384, mw, nw, kk, lane);
            mma_1prod(acc, f);
        }
    }

    // Epilogue: write context
    int gid = lane >> 2, tig = lane & 3;
    size_t base = ((size_t)(b * LSEQ + qt * 128 + mw * 32)) * DDIM
                + (size_t)dt * 128 + nw * 64;
#pragma unroll
    for (int mb = 0; mb < 2; mb++)
#pragma unroll
        for (int nb = 0; nb < 8; nb++) {
            size_t o0 = base + (size_t)(mb * 16 + gid) * DDIM + nb * 8 + tig * 2;
            *reinterpret_cast<float2*>(&ctx[o0]) =
                make_float2(acc[mb][nb][0], acc[mb][nb][1]);
            *reinterpret_cast<float2*>(&ctx[o0 + 8 * DDIM]) =
                make_float2(acc[mb][nb][2], acc[mb][nb][3]);
        }
}

// ============================================================================
// Launch: event-based fork-join (graph-capture safe; no device spin).
//   s0: convert(b0), [wait evC[b]] G1(b) x4, (join) G3 monolithic.
//   sB: transpose_conv, convert(b1..3)+evC, then G2(b) after evG1[b].
// Streams/events created per call and leaked (host-side only; ~2 calls).
// ============================================================================
extern "C" void kernel_launch(void* const* d_in, const int* in_sizes, int n_in,
                              void* d_out, int out_size) {
    (void)in_sizes; (void)n_in; (void)out_size;
    const float* query = (const float*)d_in[0];
    const float* value = (const float*)d_in[1];
    float* out = (float*)d_out;
    float* ctx  = out;               // context first
    float* attn = out + CTX_ELEMS;   // then attn

    cudaFuncSetAttribute(g1_scores,  cudaFuncAttributeMaxDynamicSharedMemorySize, SMEM_G1);
    cudaFuncSetAttribute(g3_context, cudaFuncAttributeMaxDynamicSharedMemorySize, SMEM_G3);

    cudaStream_t sB;
    cudaStreamCreateWithFlags(&sB, cudaStreamNonBlocking);
    cudaEvent_t evFork, evC[BATCH], evG1[BATCH], evJoin;
    cudaEventCreateWithFlags(&evFork, cudaEventDisableTiming);
    for (int b = 0; b < BATCH; b++) {
        cudaEventCreateWithFlags(&evC[b], cudaEventDisableTiming);
        cudaEventCreateWithFlags(&evG1[b], cudaEventDisableTiming);
    }
    cudaEventCreateWithFlags(&evJoin, cudaEventDisableTiming);

    // Fork: sB handles transpose (raw V only) + converts for batches 1..3,
    // all overlapping G1(b0) on s0.
    cudaEventRecord(evFork, 0);
    cudaStreamWaitEvent(sB, evFork, 0);
    transpose_conv<<<dim3(LSEQ / 32, DDIM / 32, BATCH), dim3(32, 8), 0, sB>>>(value);
    for (int b = 1; b < BATCH; b++) {
        convert_qv<<<BELEM / 256, 256, 0, sB>>>(query, value, b);
        cudaEventRecord(evC[b], sB);
    }

    // s0: only batch 0's convert sits on the critical path.
    convert_qv<<<BELEM / 256, 256>>>(query, value, 0);

    for (int b = 0; b < BATCH; b++) {
        if (b > 0) cudaStreamWaitEvent(0, evC[b], 0);
        g1_scores<<<dim3(64, 32), 256, SMEM_G1>>>(attn, b);
        cudaEventRecord(evG1[b], 0);
        cudaStreamWaitEvent(sB, evG1[b], 0);
        g2_softmax<<<LSEQ, 256, 0, sB>>>(attn, b);
    }

    // Join: G3 needs all of g_Ph (G2) and g_VTh (transpose).
    cudaEventRecord(evJoin, sB);
    cudaStreamWaitEvent(0, evJoin, 0);
    g3_context<<<dim3(4, 32, 4), 256, SMEM_G3>>>(ctx);
    // Streams/events intentionally leaked (capture-referenced; ~2 calls total).
}